// round 13
// baseline (speedup 1.0000x reference)
#include <cuda_runtime.h>
#include <cuda_bf16.h>
#include <cuda_fp16.h>
#include <cstdint>

#define BB 32
#define TT 512
#define DD 768
#define HH 512
#define CC 7
#define K2 2048
#define N4H 2048
#define HBUF (2*BB*HH)

// ---------------- device state ----------------
__device__ float g_enc[BB*TT*HH];          // enc_proj fp32 (33.5MB)
__device__ __half g_xh[BB*TT*DD];          // fp16 x (25MB)
__device__ uint2 g_WcatPh[2*128*256*32];   // frag-packed fp16 weights (16.7MB)
__device__ float g_bcat[2*N4H];
__device__ float g_WdecT[HH*HH];
__device__ float g_h2[2*HBUF];             // double-buffered h (step parity)
__device__ float g_c[2*BB*HH];
__device__ float g_decp[8*2*BB*HH];
__device__ float g_mp[2*4*2*BB];
__device__ float g_zp[4*2*BB];
__device__ float g_ctxp[4*2*BB*DD];
__device__ float g_gpart[8*2*BB*N4H];
__device__ float g_hs[2*TT*BB*HH];
// monotonic counters (padded 128B apart)
__device__ unsigned g_cab[64];             // [dom*32] AB done (128/step)
__device__ unsigned g_ce[64];              // [dom*32] E done (128/step)
__device__ unsigned g_cc[1024];            // [(dom*16+nt)*32] C partials (8/step)
__device__ unsigned g_cdn[1024];           // [(dom*16+nt)*32] finisher done (1/step)

// ---------------- helpers ----------------
__device__ __forceinline__ float fast_tanh(float x){
    float y; asm("tanh.approx.f32 %0, %1;" : "=f"(y) : "f"(x)); return y;
}
__device__ __forceinline__ float tanh_acc(float x){
    float e = __expf(x + x);
    return 1.0f - __fdividef(2.0f, e + 1.0f);
}
__device__ __forceinline__ float sigm(float x){ return 1.0f/(1.0f+__expf(-x)); }
__device__ __forceinline__ float warpMax(float v){
    #pragma unroll
    for(int o=16;o;o>>=1) v = fmaxf(v, __shfl_xor_sync(0xffffffffu, v, o));
    return v;
}
__device__ __forceinline__ float warpSum(float v){
    #pragma unroll
    for(int o=16;o;o>>=1) v += __shfl_xor_sync(0xffffffffu, v, o);
    return v;
}
__device__ __forceinline__ void mma_f16(float* c, const uint32_t* a, uint32_t b0, uint32_t b1){
    asm volatile("mma.sync.aligned.m16n8k16.row.col.f32.f16.f16.f32 "
                 "{%0,%1,%2,%3}, {%4,%5,%6,%7}, {%8,%9}, {%0,%1,%2,%3};"
                 : "+f"(c[0]), "+f"(c[1]), "+f"(c[2]), "+f"(c[3])
                 : "r"(a[0]), "r"(a[1]), "r"(a[2]), "r"(a[3]), "r"(b0), "r"(b1));
}
__device__ __forceinline__ void wait_ge(unsigned* p, unsigned t){
    unsigned v;
    #pragma unroll 1
    do { asm volatile("ld.acquire.gpu.u32 %0, [%1];" : "=r"(v) : "l"(p)); } while(v < t);
}
__device__ __forceinline__ void red_rel(unsigned* p){
    asm volatile("red.release.gpu.global.add.u32 [%0], %1;" :: "l"(p), "r"(1u) : "memory");
}
__device__ __forceinline__ unsigned atom_acqrel(unsigned* p){
    unsigned old;
    asm volatile("atom.acq_rel.gpu.global.add.u32 %0, [%1], %2;"
                 : "=r"(old) : "l"(p), "r"(1u) : "memory");
    return old;
}

// ---------------- init ----------------
__global__ void k_init(const float* __restrict__ b_dec){
    int i = blockIdx.x*blockDim.x + threadIdx.x;
    if(i < 64){ g_cab[i]=0u; g_ce[i]=0u; }
    if(i < 1024){ g_cc[i]=0u; g_cdn[i]=0u; }
    if(i < 2*4*2*BB) g_mp[i] = 0.f;
    if(i < 4*2*BB) g_zp[i] = 1.f;
    if(i < 2*HBUF) g_h2[i] = 0.f;
    if(i < 2*BB*HH) g_c[i] = 0.f;
    if(i < 8*2*BB*HH){
        int kc = i >> 15;
        g_decp[i] = (kc==0) ? b_dec[i & (HH-1)] : 0.f;
    }
}

// ---------------- prep ----------------
__global__ void k_prep(const float* __restrict__ Wf_ih, const float* __restrict__ Wf_hh,
                       const float* __restrict__ bf,
                       const float* __restrict__ Wb_ih, const float* __restrict__ Wb_hh,
                       const float* __restrict__ bb,
                       const float* __restrict__ W_dec,
                       const float* __restrict__ x){
    int tid0 = blockIdx.x*blockDim.x + threadIdx.x;
    int stride = gridDim.x*blockDim.x;
    for(int i = tid0; i < 2*128*256*32; i += stride){
        int lane = i & 31;
        int n8 = (i>>5) & 255;
        int k16 = (i>>13) & 127;
        int dir = (i>>20) & 1;
        int gq = lane>>2, tq = lane&3;
        int n = n8*8 + gq;
        int j = ((n&3)<<9) + (n>>2);
        const float* Wih = dir ? Wb_ih : Wf_ih;
        const float* Whh = dir ? Wb_hh : Wf_hh;
        int ka = k16*16 + 2*tq;
        int kb = ka + 8;
        float wa0 = (ka   < 1536) ? Wih[j*1536 + ka]   : Whh[j*512 + (ka-1536)];
        float wa1 = (ka+1 < 1536) ? Wih[j*1536 + ka+1] : Whh[j*512 + (ka+1-1536)];
        float wb0 = (kb   < 1536) ? Wih[j*1536 + kb]   : Whh[j*512 + (kb-1536)];
        float wb1 = (kb+1 < 1536) ? Wih[j*1536 + kb+1] : Whh[j*512 + (kb+1-1536)];
        __half2 h0 = __floats2half2_rn(wa0, wa1);
        __half2 h1 = __floats2half2_rn(wb0, wb1);
        g_WcatPh[i] = make_uint2(*(uint32_t*)&h0, *(uint32_t*)&h1);
    }
    for(int i = tid0; i < BB*TT*DD; i += stride){
        g_xh[i] = __float2half(x[i]);
    }
    if(tid0 < 2*N4H){
        int jj = tid0 & (N4H-1); int dir = tid0 >> 11;
        int j = ((jj&3)<<9) + (jj>>2);
        g_bcat[tid0] = dir ? bb[j] : bf[j];
    }
    if(tid0 < HH*HH){
        int n = tid0 & (HH-1); int k = tid0 >> 9;
        g_WdecT[k*HH + n] = W_dec[n*HH + k];
    }
}

// ---------------- enc_proj GEMM ----------------
__global__ void k_enc_gemm(const float* __restrict__ A, const float* __restrict__ Bm,
                           const float* __restrict__ bias){
    __shared__ float As[16][68];
    __shared__ float Bs[16][68];
    const int Kk = DD, Nn = HH;
    int n0 = blockIdx.x*64, m0 = blockIdx.y*64;
    int tid = threadIdx.x;
    int tm = tid>>4, tn = tid&15;
    float acc[4][4];
    #pragma unroll
    for(int i=0;i<4;i++)
        #pragma unroll
        for(int j=0;j<4;j++) acc[i][j] = bias[n0 + tn*4 + j];

    int lrow = tid>>2, lkq = (tid&3)*4;
    for(int k0=0;k0<Kk;k0+=16){
        float4 av = *(const float4*)&A[(long)(m0+lrow)*Kk + k0 + lkq];
        float4 bv = *(const float4*)&Bm[(long)(n0+lrow)*Kk + k0 + lkq];
        __syncthreads();
        As[lkq+0][lrow]=av.x; As[lkq+1][lrow]=av.y; As[lkq+2][lrow]=av.z; As[lkq+3][lrow]=av.w;
        Bs[lkq+0][lrow]=bv.x; Bs[lkq+1][lrow]=bv.y; Bs[lkq+2][lrow]=bv.z; Bs[lkq+3][lrow]=bv.w;
        __syncthreads();
        #pragma unroll
        for(int kk=0;kk<16;kk++){
            float4 a4 = *(const float4*)&As[kk][tm*4];
            float4 b4 = *(const float4*)&Bs[kk][tn*4];
            float aa[4] = {a4.x,a4.y,a4.z,a4.w};
            float bb4[4] = {b4.x,b4.y,b4.z,b4.w};
            #pragma unroll
            for(int i=0;i<4;i++)
                #pragma unroll
                for(int j=0;j<4;j++) acc[i][j] += aa[i]*bb4[j];
        }
    }
    #pragma unroll
    for(int i=0;i<4;i++)
        #pragma unroll
        for(int j=0;j<4;j++)
            g_enc[(long)(m0+tm*4+i)*Nn + n0 + tn*4 + j] = acc[i][j];
}

// ---------------- persistent kernel: barrier-free dataflow pipeline -------------
union SH {
    struct { float d0[HH], vs[HH];
             float sw0[128];
             float red0[4], red1[4]; } a;
    struct { uint32_t Ap[8192]; float zinv[32]; } c;
    struct { float Hs[32][64]; float Ws[64][32]; } e;
};

struct Ctx {
    int tid, lane, warp, dom;
};

// ---- C task (+ inline LSTM finisher) ----
__device__ __forceinline__ void run_C(SH& sh, int* s_fin, const Ctx& cx,
                                      int s, int nt, int kc, int t_cur){
    const int tid = cx.tid, lane = cx.lane, warp = cx.warp, dom = cx.dom;
    int n0 = nt*128, k0 = kc*256;
    if(tid == 0){
        wait_ge(&g_cdn[(dom*16+nt)*32], (unsigned)s);              // gpart WAW
        if(kc < 3) wait_ge(&g_cab[dom*32], 128u*(unsigned)(s+1));  // needs all AB_s
        if(kc == 6){ for(int j=0;j<8;j++)  wait_ge(&g_cdn[(dom*16+j)*32], (unsigned)s); }
        if(kc == 7){ for(int j=8;j<16;j++) wait_ge(&g_cdn[(dom*16+j)*32], (unsigned)s); }
    }
    __syncthreads();
    if(kc < 3){
        if(tid < 32){
            float z = g_zp[(0*2+dom)*BB+tid] + g_zp[(1*2+dom)*BB+tid]
                    + g_zp[(2*2+dom)*BB+tid] + g_zp[(3*2+dom)*BB+tid];
            sh.c.zinv[tid] = 1.0f / z;
        }
        __syncthreads();
    }
    // ---- fill frag-packed A (32b x 256k, fp16 pairs) ----
    const float* hrd = &g_h2[(s&1)*HBUF];
    #pragma unroll
    for(int r=0;r<8;r++){
        int idx = tid + (r<<9);
        int b = idx>>7, kp = idx&127;
        int k = k0 + kp*2;
        float v0, v1;
        if(kc < 3){
            float zi = sh.c.zinv[b];
            v0 = (g_ctxp[((0*2+dom)*BB+b)*DD + k]
                + g_ctxp[((1*2+dom)*BB+b)*DD + k]
                + g_ctxp[((2*2+dom)*BB+b)*DD + k]
                + g_ctxp[((3*2+dom)*BB+b)*DD + k]) * zi;
            v1 = (g_ctxp[((0*2+dom)*BB+b)*DD + k+1]
                + g_ctxp[((1*2+dom)*BB+b)*DD + k+1]
                + g_ctxp[((2*2+dom)*BB+b)*DD + k+1]
                + g_ctxp[((3*2+dom)*BB+b)*DD + k+1]) * zi;
        } else if(kc < 6){
            v0 = __half2float(g_xh[(long)(b*TT + t_cur)*DD + (k-768)]);
            v1 = __half2float(g_xh[(long)(b*TT + t_cur)*DD + (k+1-768)]);
        } else {
            v0 = hrd[(dom*BB+b)*HH + (k-1536)];
            v1 = hrd[(dom*BB+b)*HH + (k+1-1536)];
        }
        __half2 hv = __floats2half2_rn(v0, v1);
        int ks = kp>>3, kkp = kp&7;
        int tq = kkp&3, khalf = kkp>>2;
        int mt = b>>4, rin = b&15, gq = rin&7, hi = rin>>3;
        sh.c.Ap[(((ks*2+mt)*32 + gq*4 + tq)<<2) + khalf*2 + hi] = *(uint32_t*)&hv;
    }
    __syncthreads();

    int nw = warp>>1, kh = warp&1;
    float acc[2][2][4];
    #pragma unroll
    for(int mt=0;mt<2;mt++)
        #pragma unroll
        for(int j=0;j<2;j++)
            #pragma unroll
            for(int r=0;r<4;r++) acc[mt][j][r]=0.f;

    const uint2* Bp = g_WcatPh + ((size_t)dom*128*256*32);
    #pragma unroll
    for(int i8=0;i8<8;i8++){
        int ksg = (kh<<3) + i8;
        uint4 A0 = *(const uint4*)&sh.c.Ap[((ksg*2+0)*32 + lane)*4];
        uint4 A1 = *(const uint4*)&sh.c.Ap[((ksg*2+1)*32 + lane)*4];
        int k16g = (kc<<4) + ksg;
        #pragma unroll
        for(int j=0;j<2;j++){
            int n8g = (nt<<4) + (nw<<1) + j;
            uint2 bb2 = Bp[((size_t)k16g*256 + n8g)*32 + lane];
            mma_f16(acc[0][j], (const uint32_t*)&A0, bb2.x, bb2.y);
            mma_f16(acc[1][j], (const uint32_t*)&A1, bb2.x, bb2.y);
        }
    }
    __syncthreads();
    float* buf = (float*)sh.c.Ap;
    if(kh == 1){
        #pragma unroll
        for(int mt=0;mt<2;mt++)
            #pragma unroll
            for(int j=0;j<2;j++)
                #pragma unroll
                for(int r=0;r<4;r++)
                    buf[nw*512 + (mt*2+j)*128 + r*32 + lane] = acc[mt][j][r];
    }
    __syncthreads();
    if(kh == 0){
        int gid = lane>>2, tg = lane&3;
        #pragma unroll
        for(int mt=0;mt<2;mt++){
            #pragma unroll
            for(int j=0;j<2;j++){
                const float* bb4 = &buf[nw*512 + (mt*2+j)*128];
                float c0 = acc[mt][j][0] + bb4[0*32 + lane];
                float c1 = acc[mt][j][1] + bb4[1*32 + lane];
                float c2 = acc[mt][j][2] + bb4[2*32 + lane];
                float c3 = acc[mt][j][3] + bb4[3*32 + lane];
                int n = n0 + ((nw<<1)+j)*8 + (tg<<1);
                int br = (mt<<4) + gid;
                *(float2*)&g_gpart[((long)(kc*2+dom)*BB + br)*N4H + n]     = make_float2(c0,c1);
                *(float2*)&g_gpart[((long)(kc*2+dom)*BB + br + 8)*N4H + n] = make_float2(c2,c3);
            }
        }
    }
    __threadfence();
    __syncthreads();
    if(tid == 0)
        *s_fin = (atom_acqrel(&g_cc[(dom*16+nt)*32]) == (unsigned)(8*s+7)) ? 1 : 0;
    __syncthreads();
    if(*s_fin){
        // ---- inline LSTM pointwise for this nt slice (32 b x 32 hcols) ----
        float* hwr = &g_h2[((s+1)&1)*HBUF];
        #pragma unroll
        for(int q=tid; q<1024; q+=512){
            int b = q>>5, hcl = q&31;
            int hc = nt*32 + hcl;
            float4 gs = make_float4(0.f,0.f,0.f,0.f);
            #pragma unroll
            for(int p=0;p<8;p++){
                float4 gp = __ldcg((const float4*)&g_gpart[((long)(p*2+dom)*BB + b)*N4H + hc*4]);
                gs.x+=gp.x; gs.y+=gp.y; gs.z+=gp.z; gs.w+=gp.w;
            }
            float4 bc = *(const float4*)&g_bcat[dom*N4H + hc*4];
            float ig = sigm(gs.x+bc.x);
            float fg = sigm(gs.y+bc.y);
            float gg = tanh_acc(gs.z+bc.z);
            float og = sigm(gs.w+bc.w);
            int ix = (dom*BB+b)*HH + hc;
            float cprev = __ldcg(&g_c[ix]);
            float c = fg*cprev + ig*gg;
            float h = og*tanh_acc(c);
            g_c[ix] = c;
            hwr[ix] = h;
            g_hs[((dom*TT+t_cur)*BB + b)*HH + hc] = h;
        }
        __threadfence();
        __syncthreads();
        if(tid == 0) red_rel(&g_cdn[(dom*16+nt)*32]);
    }
}

__global__ void __launch_bounds__(512, 2)
k_persist(const float* __restrict__ x, const float* __restrict__ v,
          const float* __restrict__ b_dec, int NSM){
    __shared__ SH sh;
    __shared__ int s_fin;
    const int tid = threadIdx.x;
    const int lane = tid & 31, warp = tid >> 5;
    const int dom = (blockIdx.x >= NSM) ? 1 : 0;
    const int dbid = blockIdx.x - dom*NSM;
    Ctx cx{tid, lane, warp, dom};

    const bool hasAB = dbid < 128;
    const int cOff = NSM - 128;
    const bool hasC = dbid >= cOff;
    const int c_idx = dbid - cOff;
    const int c_nt = c_idx & 15, c_kc = c_idx >> 4;
    const bool cEarly = hasC && (c_kc >= 3);
    const int e_nt = dbid & 15, e_kc = dbid >> 4;

    for(int s=0; s<TT; s++){
        const int t_cur = dom ? (TT-1-s) : s;

        // ---- early C (x/h-fed K-slices: independent of this step's attention) --
        if(cEarly) run_C(sh, &s_fin, cx, s, c_nt, c_kc, t_cur);

        // ======== AB: scores + stale-max softmax + unnormalized ctx ============
        if(hasAB){
            int b = dbid >> 2, tp = dbid & 3;
            int t0 = tp*128;
            if(tid == 0) wait_ge(&g_ce[dom*32], 128u*(unsigned)s);
            __syncthreads();
            {
                float a0=0.f;
                #pragma unroll
                for(int kc=0;kc<8;kc++)
                    a0 += g_decp[((kc*2+dom)*BB + b)*HH + tid];
                sh.a.d0[tid]=a0; sh.a.vs[tid]=v[tid];
            }
            __syncthreads();
            #pragma unroll 1
            for(int i=0;i<8;i++){
                int tl = warp*8 + i;
                const float* e = &g_enc[(b*TT + t0 + tl)*HH];
                float s0=0.f;
                #pragma unroll
                for(int j=0;j<16;j++){
                    int h = lane + j*32;
                    s0 += sh.a.vs[h]*fast_tanh(e[h] + sh.a.d0[h]);
                }
                s0 = warpSum(s0);
                if(lane==0) sh.a.sw0[tl] = s0;
            }
            __syncthreads();
            const float* mpr = g_mp + (s&1)*256;
            float m0 = mpr[(0*2+dom)*BB+b];
            #pragma unroll
            for(int p=1;p<4;p++) m0 = fmaxf(m0, mpr[(p*2+dom)*BB+b]);
            if(tid < 128){
                float sc = sh.a.sw0[tid];
                float e = __expf(sc - m0);
                sh.a.sw0[tid] = e;
                float z = warpSum(e);
                float mx = warpMax(sc);
                if(lane==0){ sh.a.red0[warp] = z; sh.a.red1[warp] = mx; }
            }
            __syncthreads();
            if(tid == 0){
                g_zp[(tp*2+dom)*BB+b] = sh.a.red0[0]+sh.a.red0[1]+sh.a.red0[2]+sh.a.red0[3];
                g_mp[((s+1)&1)*256 + (tp*2+dom)*BB+b] =
                    fmaxf(fmaxf(sh.a.red1[0],sh.a.red1[1]),
                          fmaxf(sh.a.red1[2],sh.a.red1[3]));
            }
            __syncthreads();
            if(tid < 384){
                const __half2* xb = (const __half2*)&g_xh[(long)(b*TT + t0)*DD] + tid;
                float a0x=0.f, a0y=0.f;
                #pragma unroll 8
                for(int t=0;t<128;t++){
                    float ww0 = sh.a.sw0[t];
                    float2 xv = __half22float2(xb[(long)t*384]);
                    a0x += ww0*xv.x; a0y += ww0*xv.y;
                }
                *(float2*)&g_ctxp[((tp*2+dom)*BB + b)*DD + tid*2] = make_float2(a0x, a0y);
            }
            __threadfence();
            __syncthreads();
            if(tid == 0) red_rel(&g_cab[dom*32]);
        }

        // ---- late C (ctx-fed K-slices) ----
        if(hasC && !cEarly) run_C(sh, &s_fin, cx, s, c_nt, c_kc, t_cur);

        // ======== E: dec partials (h @ WdecT) ===================================
        if(hasAB){
            int n0 = e_nt*32, k0 = e_kc*64;
            if(tid == 0){
                wait_ge(&g_cdn[(dom*16 + 2*e_kc)*32],   (unsigned)(s+1));
                wait_ge(&g_cdn[(dom*16 + 2*e_kc+1)*32], (unsigned)(s+1));
            }
            __syncthreads();
            const float* hrd = &g_h2[((s+1)&1)*HBUF];
            #pragma unroll
            for(int r=0;r<4;r++){
                int lin = tid + 512*r;
                int bi = lin>>6, k = lin&63;
                sh.e.Hs[bi][k] = hrd[(dom*BB+bi)*HH + k0 + k];
            }
            #pragma unroll
            for(int r=0;r<4;r++){
                int lin = tid + 512*r;
                int k = lin>>5, n = lin&31;
                sh.e.Ws[k][n] = g_WdecT[(k0+k)*HH + n0 + n];
            }
            __syncthreads();
            int tb = tid>>4, tn = tid&15;
            float acc0=0.f, acc1=0.f;
            #pragma unroll 8
            for(int k=0;k<64;k++){
                float a = sh.e.Hs[tb][k];
                float2 w2 = *(const float2*)&sh.e.Ws[k][tn*2];
                acc0 += a*w2.x; acc1 += a*w2.y;
            }
            int n = n0 + tn*2;
            float bias0 = (e_kc==0) ? b_dec[n]   : 0.f;
            float bias1 = (e_kc==0) ? b_dec[n+1] : 0.f;
            g_decp[((e_kc*2+dom)*BB + tb)*HH + n]   = acc0 + bias0;
            g_decp[((e_kc*2+dom)*BB + tb)*HH + n+1] = acc1 + bias1;
            __threadfence();
            __syncthreads();
            if(tid == 0) red_rel(&g_ce[dom*32]);
        }
    }
}

// ---------------- final head ----------------
__global__ void k_head(const float* __restrict__ W_head, const float* __restrict__ b_head,
                       float* __restrict__ out){
    __shared__ float Ws[CC*2*HH];
    int tid = threadIdx.x;
    for(int i=tid;i<CC*2*HH;i+=256) Ws[i] = W_head[i];
    __syncthreads();
    int warp = tid>>5, lane = tid&31;
    int m = blockIdx.x*8 + warp;
    int b = m >> 9, t = m & (TT-1);
    const float* hf = &g_hs[((0*TT+t)*BB + b)*HH];
    const float* hb = &g_hs[((1*TT+t)*BB + b)*HH];
    float acc[CC];
    #pragma unroll
    for(int c=0;c<CC;c++) acc[c]=0.f;
    #pragma unroll 4
    for(int i=0;i<16;i++){
        int k = lane + i*32;
        float vf = hf[k];
        float vb = hb[k];
        #pragma unroll
        for(int c=0;c<CC;c++){
            acc[c] += vf*Ws[c*1024 + k] + vb*Ws[c*1024 + 512 + k];
        }
    }
    float res = 0.f;
    #pragma unroll
    for(int c=0;c<CC;c++){
        float r = warpSum(acc[c]);
        if(lane==c) res = r;
    }
    if(lane < CC) out[m*CC + lane] = res + b_head[lane];
}

// ---------------- launch ----------------
extern "C" void kernel_launch(void* const* d_in, const int* in_sizes, int n_in,
                              void* d_out, int out_size){
    const float* x      = (const float*)d_in[0];
    const float* Wf_ih  = (const float*)d_in[1];
    const float* Wf_hh  = (const float*)d_in[2];
    const float* bf     = (const float*)d_in[3];
    const float* Wb_ih  = (const float*)d_in[4];
    const float* Wb_hh  = (const float*)d_in[5];
    const float* bb     = (const float*)d_in[6];
    const float* W_enc  = (const float*)d_in[7];
    const float* b_enc  = (const float*)d_in[8];
    const float* W_dec  = (const float*)d_in[9];
    const float* b_dec  = (const float*)d_in[10];
    const float* v      = (const float*)d_in[11];
    const float* W_head = (const float*)d_in[12];
    const float* b_head = (const float*)d_in[13];
    float* out = (float*)d_out;

    int dev = 0;
    cudaGetDevice(&dev);
    int nsm = 148;
    cudaDeviceGetAttribute(&nsm, cudaDevAttrMultiProcessorCount, dev);
    if(nsm < 128) nsm = 128;

    k_init<<<1024, 256>>>(b_dec);
    k_prep<<<2048, 256>>>(Wf_ih, Wf_hh, bf, Wb_ih, Wb_hh, bb, W_dec, x);
    k_enc_gemm<<<dim3(8, 256), 256>>>(x, W_enc, b_enc);
    k_persist<<<2*nsm, 512>>>(x, v, b_dec, nsm);
    k_head<<<2048, 256>>>(W_head, b_head, out);
}

// round 14
// speedup vs baseline: 1.5139x; 1.5139x over previous
#include <cuda_runtime.h>
#include <cuda_bf16.h>
#include <cuda_fp16.h>
#include <cstdint>

#define BB 32
#define TT 512
#define DD 768
#define HH 512
#define CC 7
#define K2 2048          // gates GEMM K = ctx(768) + xt(768) + h(512)
#define N4H 2048         // 4*H

// ---------------- device state (static scratch; no allocations) ----------------
__device__ __half g_ench[BB*TT*HH];        // enc_proj fp16 (16.7MB)
__device__ __half g_xh[BB*TT*DD];          // fp16 copy of x (25MB)
__device__ uint2 g_WcatPh[2*128*256*32];   // frag-packed fp16 weights (16.7MB)
__device__ float g_bcat[2*N4H];
__device__ float g_WdecT[HH*HH];
__device__ float g_h[2*BB*HH];
__device__ float g_c[2*BB*HH];
__device__ float g_decp[8*2*BB*HH];        // [kc8][dir][b][n]
__device__ float g_mp[2*4*2*BB];           // ping-pong partial maxes
__device__ float g_zp[4*2*BB];             // partial Z
__device__ float g_ctxp[4*2*BB*DD];        // unnormalized ctx partials
__device__ float g_gpart[8*2*BB*N4H];      // gates partials (4.2MB)
__device__ float g_hs[2*TT*BB*HH];
__device__ unsigned int g_arr[64];         // two barrier counters, 128B apart

// ---------------- helpers ----------------
__device__ __forceinline__ float fast_tanh(float x){
    float y; asm("tanh.approx.f32 %0, %1;" : "=f"(y) : "f"(x)); return y;
}
__device__ __forceinline__ float tanh_acc(float x){
    float e = __expf(x + x);
    return 1.0f - __fdividef(2.0f, e + 1.0f);
}
__device__ __forceinline__ float sigm(float x){ return 1.0f/(1.0f+__expf(-x)); }
__device__ __forceinline__ float warpMax(float v){
    #pragma unroll
    for(int o=16;o;o>>=1) v = fmaxf(v, __shfl_xor_sync(0xffffffffu, v, o));
    return v;
}
__device__ __forceinline__ float warpSum(float v){
    #pragma unroll
    for(int o=16;o;o>>=1) v += __shfl_xor_sync(0xffffffffu, v, o);
    return v;
}
__device__ __forceinline__ void mma_f16(float* c, const uint32_t* a, uint32_t b0, uint32_t b1){
    asm volatile("mma.sync.aligned.m16n8k16.row.col.f32.f16.f16.f32 "
                 "{%0,%1,%2,%3}, {%4,%5,%6,%7}, {%8,%9}, {%0,%1,%2,%3};"
                 : "+f"(c[0]), "+f"(c[1]), "+f"(c[2]), "+f"(c[3])
                 : "r"(a[0]), "r"(a[1]), "r"(a[2]), "r"(a[3]), "r"(b0), "r"(b1));
}

// ---------------- per-domain grid barrier (monotonic, busy spin) ----------------
__device__ __forceinline__ void gbar(int dom, unsigned int target){
    __syncthreads();
    if(threadIdx.x == 0){
        unsigned int* ctr = &g_arr[dom<<5];
        asm volatile("red.release.gpu.global.add.u32 [%0], %1;"
                     :: "l"(ctr), "r"(1u) : "memory");
        unsigned int vv;
        #pragma unroll 1
        do {
            asm volatile("ld.acquire.gpu.u32 %0, [%1];" : "=r"(vv) : "l"(ctr));
        } while(vv < target);
    }
    __syncthreads();
}

// ---------------- init ----------------------------------------------------------
__global__ void k_init(const float* __restrict__ b_dec){
    int i = blockIdx.x*blockDim.x + threadIdx.x;
    if(i < 64) g_arr[i] = 0u;
    if(i < 2*4*2*BB) g_mp[i] = 0.f;
    if(i < 4*2*BB) g_zp[i] = 1.f;
    if(i < 2*BB*HH){ g_h[i]=0.f; g_c[i]=0.f; }
    if(i < 8*2*BB*HH){
        int kc = i >> 15;
        g_decp[i] = (kc==0) ? b_dec[i & (HH-1)] : 0.f;
    }
}

// ---------------- prep ----------------------------------------------------------
__global__ void k_prep(const float* __restrict__ Wf_ih, const float* __restrict__ Wf_hh,
                       const float* __restrict__ bf,
                       const float* __restrict__ Wb_ih, const float* __restrict__ Wb_hh,
                       const float* __restrict__ bb,
                       const float* __restrict__ W_dec,
                       const float* __restrict__ x){
    int tid0 = blockIdx.x*blockDim.x + threadIdx.x;
    int stride = gridDim.x*blockDim.x;
    for(int i = tid0; i < 2*128*256*32; i += stride){
        int lane = i & 31;
        int n8 = (i>>5) & 255;
        int k16 = (i>>13) & 127;
        int dir = (i>>20) & 1;
        int gq = lane>>2, tq = lane&3;
        int n = n8*8 + gq;
        int j = ((n&3)<<9) + (n>>2);
        const float* Wih = dir ? Wb_ih : Wf_ih;
        const float* Whh = dir ? Wb_hh : Wf_hh;
        int ka = k16*16 + 2*tq;
        int kb = ka + 8;
        float wa0 = (ka   < 1536) ? Wih[j*1536 + ka]   : Whh[j*512 + (ka-1536)];
        float wa1 = (ka+1 < 1536) ? Wih[j*1536 + ka+1] : Whh[j*512 + (ka+1-1536)];
        float wb0 = (kb   < 1536) ? Wih[j*1536 + kb]   : Whh[j*512 + (kb-1536)];
        float wb1 = (kb+1 < 1536) ? Wih[j*1536 + kb+1] : Whh[j*512 + (kb+1-1536)];
        __half2 h0 = __floats2half2_rn(wa0, wa1);
        __half2 h1 = __floats2half2_rn(wb0, wb1);
        g_WcatPh[i] = make_uint2(*(uint32_t*)&h0, *(uint32_t*)&h1);
    }
    for(int i = tid0; i < BB*TT*DD; i += stride){
        g_xh[i] = __float2half(x[i]);
    }
    if(tid0 < 2*N4H){
        int jj = tid0 & (N4H-1); int dir = tid0 >> 11;
        int j = ((jj&3)<<9) + (jj>>2);
        g_bcat[tid0] = dir ? bb[j] : bf[j];
    }
    if(tid0 < HH*HH){
        int n = tid0 & (HH-1); int k = tid0 >> 9;
        g_WdecT[k*HH + n] = W_dec[n*HH + k];
    }
}

// ---------------- enc_proj GEMM (fp16 out) --------------------------------------
__global__ void k_enc_gemm(const float* __restrict__ A, const float* __restrict__ Bm,
                           const float* __restrict__ bias){
    __shared__ float As[16][68];
    __shared__ float Bs[16][68];
    const int Kk = DD, Nn = HH;
    int n0 = blockIdx.x*64, m0 = blockIdx.y*64;
    int tid = threadIdx.x;
    int tm = tid>>4, tn = tid&15;
    float acc[4][4];
    #pragma unroll
    for(int i=0;i<4;i++)
        #pragma unroll
        for(int j=0;j<4;j++) acc[i][j] = bias[n0 + tn*4 + j];

    int lrow = tid>>2, lkq = (tid&3)*4;
    for(int k0=0;k0<Kk;k0+=16){
        float4 av = *(const float4*)&A[(long)(m0+lrow)*Kk + k0 + lkq];
        float4 bv = *(const float4*)&Bm[(long)(n0+lrow)*Kk + k0 + lkq];
        __syncthreads();
        As[lkq+0][lrow]=av.x; As[lkq+1][lrow]=av.y; As[lkq+2][lrow]=av.z; As[lkq+3][lrow]=av.w;
        Bs[lkq+0][lrow]=bv.x; Bs[lkq+1][lrow]=bv.y; Bs[lkq+2][lrow]=bv.z; Bs[lkq+3][lrow]=bv.w;
        __syncthreads();
        #pragma unroll
        for(int kk=0;kk<16;kk++){
            float4 a4 = *(const float4*)&As[kk][tm*4];
            float4 b4 = *(const float4*)&Bs[kk][tn*4];
            float aa[4] = {a4.x,a4.y,a4.z,a4.w};
            float bb4[4] = {b4.x,b4.y,b4.z,b4.w};
            #pragma unroll
            for(int i=0;i<4;i++)
                #pragma unroll
                for(int j=0;j<4;j++) acc[i][j] += aa[i]*bb4[j];
        }
    }
    #pragma unroll
    for(int i=0;i<4;i++)
        #pragma unroll
        for(int j=0;j<4;j++)
            g_ench[(long)(m0+tm*4+i)*Nn + n0 + tn*4 + j] = __float2half(acc[i][j]);
}

// ---------------- persistent recurrent kernel: 2 domains x 512 threads ----------
union SH {
    struct { float d0[HH], vs[HH];
             float sw0[128];
             float red0[4], red1[4]; } a;
    struct { uint32_t Ap[8192]; float zinv[32]; } c;                 // 32.1KB
    struct { float Hs[32][64]; float Ws[64][32]; } e;                // 16KB
};

__global__ void __launch_bounds__(512, 2)
k_persist(const float* __restrict__ x, const float* __restrict__ v,
          const float* __restrict__ b_dec, int NSM){
    __shared__ SH sh;
    const int tid = threadIdx.x;
    const int lane = tid & 31, warp = tid >> 5;
    const int dom = (blockIdx.x >= NSM) ? 1 : 0;      // 0=fwd, 1=bwd
    const int dbid = blockIdx.x - dom*NSM;
    unsigned int bt = (unsigned)NSM;

    for(int s=0; s<TT; s++){
        const int t_cur = dom ? (TT-1-s) : s;

        // ======== Phase AB: scores + stale-max softmax + unnormalized ctx =======
        for(int task = dbid; task < 128; task += NSM){
            int b = task >> 2, tp = task & 3;
            int t0 = tp*128;
            {
                float a0=0.f;
                #pragma unroll
                for(int kc=0;kc<8;kc++)
                    a0 += g_decp[((kc*2+dom)*BB + b)*HH + tid];
                sh.a.d0[tid]=a0; sh.a.vs[tid]=v[tid];
            }
            __syncthreads();
            #pragma unroll 1
            for(int i=0;i<8;i++){
                int tl = warp*8 + i;
                const __half* e = &g_ench[(long)(b*TT + t0 + tl)*HH];
                float s0=0.f;
                #pragma unroll
                for(int j=0;j<2;j++){
                    int h0 = lane*8 + j*256;
                    uint4 ev4 = *(const uint4*)&e[h0];
                    const __half2* eh = (const __half2*)&ev4;
                    float4 d01 = *(const float4*)&sh.a.d0[h0];
                    float4 d23 = *(const float4*)&sh.a.d0[h0+4];
                    float4 v01 = *(const float4*)&sh.a.vs[h0];
                    float4 v23 = *(const float4*)&sh.a.vs[h0+4];
                    float2 e0 = __half22float2(eh[0]);
                    float2 e1 = __half22float2(eh[1]);
                    float2 e2 = __half22float2(eh[2]);
                    float2 e3 = __half22float2(eh[3]);
                    s0 += v01.x*fast_tanh(e0.x + d01.x) + v01.y*fast_tanh(e0.y + d01.y);
                    s0 += v01.z*fast_tanh(e1.x + d01.z) + v01.w*fast_tanh(e1.y + d01.w);
                    s0 += v23.x*fast_tanh(e2.x + d23.x) + v23.y*fast_tanh(e2.y + d23.y);
                    s0 += v23.z*fast_tanh(e3.x + d23.z) + v23.w*fast_tanh(e3.y + d23.w);
                }
                s0 = warpSum(s0);
                if(lane==0) sh.a.sw0[tl] = s0;
            }
            __syncthreads();
            const float* mpr = g_mp + (s&1)*256;
            float m0 = mpr[(0*2+dom)*BB+b];
            #pragma unroll
            for(int p=1;p<4;p++) m0 = fmaxf(m0, mpr[(p*2+dom)*BB+b]);
            if(tid < 128){
                float sc = sh.a.sw0[tid];
                float e = __expf(sc - m0);
                sh.a.sw0[tid] = e;
                float z = warpSum(e);
                float mx = warpMax(sc);
                if(lane==0){ sh.a.red0[warp] = z; sh.a.red1[warp] = mx; }
            }
            __syncthreads();
            if(tid == 0){
                g_zp[(tp*2+dom)*BB+b] = sh.a.red0[0]+sh.a.red0[1]+sh.a.red0[2]+sh.a.red0[3];
                g_mp[((s+1)&1)*256 + (tp*2+dom)*BB+b] =
                    fmaxf(fmaxf(sh.a.red1[0],sh.a.red1[1]),
                          fmaxf(sh.a.red1[2],sh.a.red1[3]));
            }
            __syncthreads();
            if(tid < 384){
                const __half2* xb = (const __half2*)&g_xh[(long)(b*TT + t0)*DD] + tid;
                float a0x=0.f, a0y=0.f;
                #pragma unroll 8
                for(int t=0;t<128;t++){
                    float ww0 = sh.a.sw0[t];
                    float2 xv = __half22float2(xb[(long)t*384]);
                    a0x += ww0*xv.x; a0y += ww0*xv.y;
                }
                *(float2*)&g_ctxp[((tp*2+dom)*BB + b)*DD + tid*2] = make_float2(a0x, a0y);
            }
            __syncthreads();
        }
        gbar(dom, bt); bt += NSM;

        // ======== Phase C: gates GEMM via fp16 mma (128 tasks: nt16 x kc8) ======
        for(int task = dbid; task < 128; task += NSM){
            int nt = task & 15, kc = task >> 4;
            int n0 = nt*128, k0 = kc*256;

            __syncthreads();
            if(tid < 32){
                float z = g_zp[(0*2+dom)*BB+tid] + g_zp[(1*2+dom)*BB+tid]
                        + g_zp[(2*2+dom)*BB+tid] + g_zp[(3*2+dom)*BB+tid];
                sh.c.zinv[tid] = 1.0f / z;
            }
            __syncthreads();
            // ---- fill frag-packed A (32b x 256k, fp16 pairs, vectorized) ----
            #pragma unroll
            for(int r=0;r<8;r++){
                int idx = tid + (r<<9);
                int b = idx>>7, kp = idx&127;
                int k = k0 + kp*2;
                __half2 hv;
                if(kc < 3){
                    float zi = sh.c.zinv[b];
                    float2 c0 = *(const float2*)&g_ctxp[((0*2+dom)*BB+b)*DD + k];
                    float2 c1 = *(const float2*)&g_ctxp[((1*2+dom)*BB+b)*DD + k];
                    float2 c2 = *(const float2*)&g_ctxp[((2*2+dom)*BB+b)*DD + k];
                    float2 c3 = *(const float2*)&g_ctxp[((3*2+dom)*BB+b)*DD + k];
                    hv = __floats2half2_rn((c0.x+c1.x+c2.x+c3.x)*zi,
                                           (c0.y+c1.y+c2.y+c3.y)*zi);
                } else if(kc < 6){
                    hv = *(const __half2*)&g_xh[(long)(b*TT + t_cur)*DD + (k-768)];
                } else {
                    float2 h2 = *(const float2*)&g_h[(dom*BB+b)*HH + (k-1536)];
                    hv = __floats2half2_rn(h2.x, h2.y);
                }
                int ks = kp>>3, kkp = kp&7;
                int tq = kkp&3, khalf = kkp>>2;
                int mt = b>>4, rin = b&15, gq = rin&7, hi = rin>>3;
                sh.c.Ap[(((ks*2+mt)*32 + gq*4 + tq)<<2) + khalf*2 + hi] = *(uint32_t*)&hv;
            }
            __syncthreads();

            int nw = warp>>1, kh = warp&1;     // 8 n-warps x 2 k-halves
            float acc[2][2][4];
            #pragma unroll
            for(int mt=0;mt<2;mt++)
                #pragma unroll
                for(int j=0;j<2;j++)
                    #pragma unroll
                    for(int r=0;r<4;r++) acc[mt][j][r]=0.f;

            const uint2* Bp = g_WcatPh + ((size_t)dom*128*256*32);

            #pragma unroll
            for(int i8=0;i8<8;i8++){
                int ksg = (kh<<3) + i8;
                uint4 A0 = *(const uint4*)&sh.c.Ap[((ksg*2+0)*32 + lane)*4];
                uint4 A1 = *(const uint4*)&sh.c.Ap[((ksg*2+1)*32 + lane)*4];
                int k16g = (kc<<4) + ksg;
                #pragma unroll
                for(int j=0;j<2;j++){
                    int n8g = (nt<<4) + (nw<<1) + j;
                    uint2 bb2 = Bp[((size_t)k16g*256 + n8g)*32 + lane];
                    mma_f16(acc[0][j], (const uint32_t*)&A0, bb2.x, bb2.y);
                    mma_f16(acc[1][j], (const uint32_t*)&A1, bb2.x, bb2.y);
                }
            }
            __syncthreads();
            float* buf = (float*)sh.c.Ap;
            if(kh == 1){
                #pragma unroll
                for(int mt=0;mt<2;mt++)
                    #pragma unroll
                    for(int j=0;j<2;j++)
                        #pragma unroll
                        for(int r=0;r<4;r++)
                            buf[nw*512 + (mt*2+j)*128 + r*32 + lane] = acc[mt][j][r];
            }
            __syncthreads();
            if(kh == 0){
                int gid = lane>>2, tg = lane&3;
                #pragma unroll
                for(int mt=0;mt<2;mt++){
                    #pragma unroll
                    for(int j=0;j<2;j++){
                        const float* bb4 = &buf[nw*512 + (mt*2+j)*128];
                        float c0 = acc[mt][j][0] + bb4[0*32 + lane];
                        float c1 = acc[mt][j][1] + bb4[1*32 + lane];
                        float c2 = acc[mt][j][2] + bb4[2*32 + lane];
                        float c3 = acc[mt][j][3] + bb4[3*32 + lane];
                        int n = n0 + ((nw<<1)+j)*8 + (tg<<1);
                        int br = (mt<<4) + gid;
                        *(float2*)&g_gpart[((long)(kc*2+dom)*BB + br)*N4H + n]     = make_float2(c0,c1);
                        *(float2*)&g_gpart[((long)(kc*2+dom)*BB + br + 8)*N4H + n] = make_float2(c2,c3);
                    }
                }
            }
            __syncthreads();
        }
        gbar(dom, bt); bt += NSM;

        // ======== Phase D: LSTM pointwise (grid-strided over domain) ============
        for(int idx = dbid*512 + tid; idx < BB*HH; idx += NSM*512){
            int hc = idx & (HH-1);
            int b  = idx>>9;
            float4 gs = make_float4(0.f,0.f,0.f,0.f);
            #pragma unroll
            for(int p=0;p<8;p++){
                float4 gp = *(const float4*)&g_gpart[((long)(p*2+dom)*BB + b)*N4H + hc*4];
                gs.x+=gp.x; gs.y+=gp.y; gs.z+=gp.z; gs.w+=gp.w;
            }
            float4 bc = *(const float4*)&g_bcat[dom*N4H + hc*4];
            float ig = sigm(gs.x+bc.x);
            float fg = sigm(gs.y+bc.y);
            float gg = tanh_acc(gs.z+bc.z);
            float og = sigm(gs.w+bc.w);
            int ix = (dom*BB+b)*HH + hc;
            float c = fg*g_c[ix] + ig*gg;
            float h = og*tanh_acc(c);
            g_c[ix]=c; g_h[ix]=h;
            g_hs[((dom*TT+t_cur)*BB + b)*HH + hc] = h;
        }
        gbar(dom, bt); bt += NSM;

        // ======== Phase E: dec partials (h @ WdecT), 128 tasks: nt16 x kc8 ======
        for(int task = dbid; task < 128; task += NSM){
            int nt = task & 15, kc = task >> 4;
            int n0 = nt*32, k0 = kc*64;
            #pragma unroll
            for(int r=0;r<4;r++){
                int lin = tid + 512*r;
                int bi = lin>>6, k = lin&63;
                sh.e.Hs[bi][k] = g_h[(dom*BB+bi)*HH + k0 + k];
            }
            #pragma unroll
            for(int r=0;r<4;r++){
                int lin = tid + 512*r;
                int k = lin>>5, n = lin&31;
                sh.e.Ws[k][n] = g_WdecT[(k0+k)*HH + n0 + n];
            }
            __syncthreads();
            int tb = tid>>4, tn = tid&15;
            float acc0=0.f, acc1=0.f;
            #pragma unroll 8
            for(int k=0;k<64;k++){
                float a = sh.e.Hs[tb][k];
                float2 w2 = *(const float2*)&sh.e.Ws[k][tn*2];
                acc0 += a*w2.x; acc1 += a*w2.y;
            }
            int n = n0 + tn*2;
            float bias0 = (kc==0) ? b_dec[n]   : 0.f;
            float bias1 = (kc==0) ? b_dec[n+1] : 0.f;
            g_decp[((kc*2+dom)*BB + tb)*HH + n]   = acc0 + bias0;
            g_decp[((kc*2+dom)*BB + tb)*HH + n+1] = acc1 + bias1;
            __syncthreads();
        }
        gbar(dom, bt); bt += NSM;
    }
}

// ---------------- final head ----------------------------------------------------
__global__ void k_head(const float* __restrict__ W_head, const float* __restrict__ b_head,
                       float* __restrict__ out){
    __shared__ float Ws[CC*2*HH];
    int tid = threadIdx.x;
    for(int i=tid;i<CC*2*HH;i+=256) Ws[i] = W_head[i];
    __syncthreads();
    int warp = tid>>5, lane = tid&31;
    int m = blockIdx.x*8 + warp;
    int b = m >> 9, t = m & (TT-1);
    const float* hf = &g_hs[((0*TT+t)*BB + b)*HH];
    const float* hb = &g_hs[((1*TT+t)*BB + b)*HH];
    float acc[CC];
    #pragma unroll
    for(int c=0;c<CC;c++) acc[c]=0.f;
    #pragma unroll 4
    for(int i=0;i<16;i++){
        int k = lane + i*32;
        float vf = hf[k];
        float vb = hb[k];
        #pragma unroll
        for(int c=0;c<CC;c++){
            acc[c] += vf*Ws[c*1024 + k] + vb*Ws[c*1024 + 512 + k];
        }
    }
    float res = 0.f;
    #pragma unroll
    for(int c=0;c<CC;c++){
        float r = warpSum(acc[c]);
        if(lane==c) res = r;
    }
    if(lane < CC) out[m*CC + lane] = res + b_head[lane];
}

// ---------------- launch ----------------
extern "C" void kernel_launch(void* const* d_in, const int* in_sizes, int n_in,
                              void* d_out, int out_size){
    const float* x      = (const float*)d_in[0];
    const float* Wf_ih  = (const float*)d_in[1];
    const float* Wf_hh  = (const float*)d_in[2];
    const float* bf     = (const float*)d_in[3];
    const float* Wb_ih  = (const float*)d_in[4];
    const float* Wb_hh  = (const float*)d_in[5];
    const float* bb     = (const float*)d_in[6];
    const float* W_enc  = (const float*)d_in[7];
    const float* b_enc  = (const float*)d_in[8];
    const float* W_dec  = (const float*)d_in[9];
    const float* b_dec  = (const float*)d_in[10];
    const float* v      = (const float*)d_in[11];
    const float* W_head = (const float*)d_in[12];
    const float* b_head = (const float*)d_in[13];
    float* out = (float*)d_out;

    int dev = 0;
    cudaGetDevice(&dev);
    int nsm = 128;
    cudaDeviceGetAttribute(&nsm, cudaDevAttrMultiProcessorCount, dev);

    k_init<<<1024, 256>>>(b_dec);
    k_prep<<<2048, 256>>>(Wf_ih, Wf_hh, bf, Wb_ih, Wb_hh, bb, W_dec, x);
    k_enc_gemm<<<dim3(8, 256), 256>>>(x, W_enc, b_enc);
    k_persist<<<2*nsm, 512>>>(x, v, b_dec, nsm);
    k_head<<<2048, 256>>>(W_head, b_head, out);
}